// round 5
// baseline (speedup 1.0000x reference)
#include <cuda_runtime.h>

#define CCH 256        // channels (all levels)
#define NIMG 2         // batch
#define NBINS 49       // 7*7
#define SPITCH 260     // staging pitch in floats (CCH+4): 16B-aligned
#define SPITCH4 65     // pitch in float4
#define T_CTAS 43520   // transpose CTAs: 512(L3)+2048(L2)+8192(L1)+32768(L0)

// NHWC scratch for all 4 levels (float):
// L0: 2*256*256*256 = 33,554,432  @ 0
// L1: 2*128*128*256 =  8,388,608  @ 33,554,432
// L2: 2* 64* 64*256 =  2,097,152  @ 41,943,040
// L3: 2* 32* 32*256 =    524,288  @ 44,040,192
__device__ float g_nhwc[44564480];
__device__ unsigned int g_ready[4];    // finished transpose CTAs per level

__constant__ long long c_lvl_off[4] = {0LL, 33554432LL, 41943040LL, 44040192LL};
__constant__ unsigned int c_need[4] = {32768u, 8192u, 2048u, 512u};

__global__ void init_flags()
{
    if (threadIdx.x < 4) g_ready[threadIdx.x] = 0u;
}

// ---------------------------------------------------------------------------
// Pool helpers (same math as R4)
// ---------------------------------------------------------------------------
__device__ __forceinline__ void pool_phase_compute(
    const float4* __restrict__ base4, float4* __restrict__ s4,
    const int (&i0)[2][14], const int (&i1)[2][14],
    const float (&wh)[2][14], const float (&wl)[2][14],
    int Wd, int q, int bs, int b0, int bcnt)
{
    for (int bb = bs; bb < bcnt; bb += 4) {
        const int bin = b0 + bb;
        const int py  = bin / 7;
        const int px  = bin - py * 7;
        float4 acc = make_float4(0.f, 0.f, 0.f, 0.f);
#pragma unroll
        for (int sy = 0; sy < 2; ++sy) {
            const int   iy = py * 2 + sy;
            const int   r0 = i0[1][iy] * Wd;
            const int   r1 = i1[1][iy] * Wd;
            const float hy = wh[1][iy];
            const float ly = wl[1][iy];
#pragma unroll
            for (int sx = 0; sx < 2; ++sx) {
                const int   ix = px * 2 + sx;
                const int   x0 = i0[0][ix];
                const int   x1 = i1[0][ix];
                const float hx = wh[0][ix];
                const float lx = wl[0][ix];
                const float w00 = hy * hx, w01 = hy * lx;
                const float w10 = ly * hx, w11 = ly * lx;
                const float4 v00 = __ldg(base4 + (size_t)(r0 + x0) * 64);
                const float4 v01 = __ldg(base4 + (size_t)(r0 + x1) * 64);
                const float4 v10 = __ldg(base4 + (size_t)(r1 + x0) * 64);
                const float4 v11 = __ldg(base4 + (size_t)(r1 + x1) * 64);
                acc.x += w00 * v00.x + w01 * v01.x + w10 * v10.x + w11 * v11.x;
                acc.y += w00 * v00.y + w01 * v01.y + w10 * v10.y + w11 * v11.y;
                acc.z += w00 * v00.z + w01 * v01.z + w10 * v10.z + w11 * v11.z;
                acc.w += w00 * v00.w + w01 * v01.w + w10 * v10.w + w11 * v11.w;
            }
        }
        acc.x *= 0.25f; acc.y *= 0.25f; acc.z *= 0.25f; acc.w *= 0.25f;
        s4[bb * SPITCH4 + q] = acc;
    }
}

template <int BCNT>
__device__ __forceinline__ void pool_phase_dump(
    const float* __restrict__ s_out, float* __restrict__ outm, int b0, int tid)
{
    const int cnt = BCNT * CCH;
    for (int i = tid; i < cnt; i += 256) {
        const int c  = i / BCNT;
        const int bb = i - c * BCNT;
        outm[c * NBINS + b0 + bb] = s_out[bb * SPITCH + c];
    }
}

// ---------------------------------------------------------------------------
// ONE fused kernel: bids [0,T_CTAS) transpose (level order L3,L2,L1,L0),
// bids >= T_CTAS pool one box each, gated on per-level ready counters.
// ---------------------------------------------------------------------------
__global__ __launch_bounds__(256) void fused_kernel(
    const float* __restrict__ f0, const float* __restrict__ f1,
    const float* __restrict__ f2, const float* __restrict__ f3,
    const float* __restrict__ boxes, float* __restrict__ out, int R)
{
    __shared__ float s_buf[25 * SPITCH];           // 26,000 B (pool staging / transpose tile)
    __shared__ int   s_i0[2][14], s_i1[2][14];
    __shared__ float s_h[2][14],  s_l[2][14];

    const int bid = blockIdx.x;
    const int tid = threadIdx.x;

    if (bid < T_CTAS) {
        // ---------------- transpose tile ----------------
        int lvl, r, tl2;
        const float* src;
        if (bid < 512)        { lvl = 3; r = bid;         tl2 = 5;  src = f3; }
        else if (bid < 2560)  { lvl = 2; r = bid - 512;   tl2 = 7;  src = f2; }
        else if (bid < 10752) { lvl = 1; r = bid - 2560;  tl2 = 9;  src = f1; }
        else                  { lvl = 0; r = bid - 10752; tl2 = 11; src = f0; }

        const int t    = r & ((1 << tl2) - 1);
        const int rest = r >> tl2;
        const int c0   = (rest & 7) * 32;
        const int n    = rest >> 3;
        const int Hs   = 256 >> lvl;
        const int HW   = Hs * Hs;
        const int hw0  = t * 32;
        const int tx   = tid & 7;
        const int ty   = tid >> 3;

        const float* s = src + (size_t)n * CCH * HW;
        float* dst = g_nhwc + c_lvl_off[lvl] + (size_t)n * HW * CCH;

        float (*tile)[33] = reinterpret_cast<float (*)[33]>(s_buf);

        const float4 v = *reinterpret_cast<const float4*>(
            s + (size_t)(c0 + ty) * HW + hw0 + tx * 4);
        tile[ty][tx * 4 + 0] = v.x;
        tile[ty][tx * 4 + 1] = v.y;
        tile[ty][tx * 4 + 2] = v.z;
        tile[ty][tx * 4 + 3] = v.w;
        __syncthreads();

        float4 o;
        o.x = tile[tx * 4 + 0][ty];
        o.y = tile[tx * 4 + 1][ty];
        o.z = tile[tx * 4 + 2][ty];
        o.w = tile[tx * 4 + 3][ty];
        *reinterpret_cast<float4*>(dst + (size_t)(hw0 + ty) * CCH + c0 + tx * 4) = o;

        __threadfence();        // release: my store visible before the count bump
        __syncthreads();
        if (tid == 0) atomicAdd(&g_ready[lvl], 1u);
        return;
    }

    // ---------------- pool one box ----------------
    const int m = bid - T_CTAS;

    const float bx1 = __ldg(boxes + 4 * m + 0);
    const float by1 = __ldg(boxes + 4 * m + 1);
    const float bx2 = __ldg(boxes + 4 * m + 2);
    const float by2 = __ldg(boxes + 4 * m + 3);

    const float area = fmaxf((bx2 - bx1) * (by2 - by1), 0.0f);
    const float sz   = sqrtf(area);
    int lvl = (int)floorf(4.0f + log2f(sz / 224.0f + 1e-8f));
    lvl = min(max(lvl, 2), 5) - 2;                 // 0..3

    // gate on this level's transpose completion (acquire)
    if (tid == 0) {
        const unsigned int need = c_need[lvl];
        unsigned int v;
        do {
            asm volatile("ld.acquire.gpu.u32 %0, [%1];"
                         : "=r"(v) : "l"(&g_ready[lvl]) : "memory");
            if (v >= need) break;
            __nanosleep(256);
        } while (true);
    }
    __syncthreads();

    const int   Hd    = 256 >> lvl;
    const int   Wd    = Hd;
    const float scale = 0.25f / (float)(1 << lvl);
    const int   n     = m / R;

    const float* fbase = g_nhwc + c_lvl_off[lvl] + (size_t)n * Hd * Wd * CCH;

    if (tid < 28) {
        const int axis = tid / 14;                 // 0 = x, 1 = y
        const int k    = tid - axis * 14;
        const float c1 = axis ? by1 : bx1;
        const float c2 = axis ? by2 : bx2;
        const int  lim = Hd;
        const float start = c1 * scale - 0.5f;
        const float bsz   = (c2 * scale - 0.5f - start) * (1.0f / 7.0f);
        const float off   = (float)(k >> 1) + ((k & 1) ? 0.75f : 0.25f);
        const float t     = start + off * bsz;
        const bool  v     = (t >= -1.0f) && (t <= (float)lim);
        const float tc    = fminf(fmaxf(t, 0.0f), (float)(lim - 1));
        const int   i0    = (int)tc;
        const int   i1    = min(i0 + 1, lim - 1);
        const float l     = tc - (float)i0;
        s_i0[axis][k] = i0;
        s_i1[axis][k] = i1;
        s_l[axis][k]  = v ? l : 0.0f;
        s_h[axis][k]  = v ? (1.0f - l) : 0.0f;
    }
    __syncthreads();

    const int q  = tid & 63;
    const int bs = tid >> 6;
    const float4* base4 = reinterpret_cast<const float4*>(fbase) + q;
    float4* s4  = reinterpret_cast<float4*>(s_buf);
    float* outm = out + (size_t)m * (NBINS * CCH);

    // phase 0: bins [0,25)
    pool_phase_compute(base4, s4, s_i0, s_i1, s_h, s_l, Wd, q, bs, 0, 25);
    __syncthreads();
    pool_phase_dump<25>(s_buf, outm, 0, tid);
    __syncthreads();

    // phase 1: bins [25,49)
    pool_phase_compute(base4, s4, s_i0, s_i1, s_h, s_l, Wd, q, bs, 25, 24);
    __syncthreads();
    pool_phase_dump<24>(s_buf, outm, 25, tid);
}

// ---------------------------------------------------------------------------
extern "C" void kernel_launch(void* const* d_in, const int* in_sizes, int n_in,
                              void* d_out, int out_size)
{
    const float* f0    = (const float*)d_in[0];
    const float* f1    = (const float*)d_in[1];
    const float* f2    = (const float*)d_in[2];
    const float* f3    = (const float*)d_in[3];
    const float* boxes = (const float*)d_in[4];
    float*       out   = (float*)d_out;

    const int M = in_sizes[4] / 4;   // 1024 boxes
    const int R = M / NIMG;          // 512 per image

    init_flags<<<1, 32>>>();
    fused_kernel<<<T_CTAS + M, 256>>>(f0, f1, f2, f3, boxes, out, R);
}

// round 6
// speedup vs baseline: 2.0977x; 2.0977x over previous
#include <cuda_runtime.h>
#include <cuda_fp16.h>

#define CCH 256        // channels (all levels)
#define NIMG 2         // batch
#define NBINS 49       // 7*7
#define SPITCH 260     // staging pitch in floats (CCH+4): 16B-aligned
#define T_CTAS 2720

// NHWC fp16 scratch for all 4 levels (element offsets unchanged from fp32 layout):
// L0 @ 0, L1 @ 33,554,432, L2 @ 41,943,040, L3 @ 44,040,192 (44,564,480 halves = 89 MB)
__device__ __half g_nhwc[44564480];

__constant__ long long c_lvl_off[4] = {0LL, 33554432LL, 41943040LL, 44040192LL};

// ---------------------------------------------------------------------------
// Fused NCHW(fp32) -> NHWC(fp16) transpose for all 4 levels in ONE launch.
// blockIdx.x: L0 tiles [0,2048), L1 [2048,2560), L2 [2560,2688), L3 [2688,2720).
// blockIdx.y = channel tile (8), blockIdx.z = image (2). Block (8,32).
// Load float4 along HW; store half4 (uint2) along C.
// ---------------------------------------------------------------------------
__global__ __launch_bounds__(256) void transpose_fused(
    const float* __restrict__ f0, const float* __restrict__ f1,
    const float* __restrict__ f2, const float* __restrict__ f3)
{
    __shared__ float tile[32][33];

    const int bx = blockIdx.x;
    int lvl, t;
    const float* src;
    if (bx < 2048)      { lvl = 0; t = bx;        src = f0; }
    else if (bx < 2560) { lvl = 1; t = bx - 2048; src = f1; }
    else if (bx < 2688) { lvl = 2; t = bx - 2560; src = f2; }
    else                { lvl = 3; t = bx - 2688; src = f3; }

    const int HW  = (256 >> lvl) * (256 >> lvl);
    const int hw0 = t * 32;
    const int c0  = blockIdx.y * 32;
    const int n   = blockIdx.z;
    const int tx  = threadIdx.x;   // 0..7
    const int ty  = threadIdx.y;   // 0..31

    const float* s = src + (size_t)n * CCH * HW;
    __half* dst = g_nhwc + c_lvl_off[lvl] + (size_t)n * HW * CCH;

    {
        const float4 v = *reinterpret_cast<const float4*>(
            s + (size_t)(c0 + ty) * HW + hw0 + tx * 4);
        tile[ty][tx * 4 + 0] = v.x;
        tile[ty][tx * 4 + 1] = v.y;
        tile[ty][tx * 4 + 2] = v.z;
        tile[ty][tx * 4 + 3] = v.w;
    }
    __syncthreads();

    {
        const __half2 a = __floats2half2_rn(tile[tx * 4 + 0][ty], tile[tx * 4 + 1][ty]);
        const __half2 b = __floats2half2_rn(tile[tx * 4 + 2][ty], tile[tx * 4 + 3][ty]);
        uint2 o;
        o.x = *reinterpret_cast<const unsigned int*>(&a);
        o.y = *reinterpret_cast<const unsigned int*>(&b);
        *reinterpret_cast<uint2*>(dst + (size_t)(hw0 + ty) * CCH + c0 + tx * 4) = o;
    }
}

// ---------------------------------------------------------------------------
// ROIAlign pooler over fp16 NHWC scratch. One CTA per box. 256 threads:
//   q  = tid & 31  -> channel oct (8 halves = one uint4), coalesced per warp
//   bs = tid >> 5  -> bin set (8 sets strided over the phase's bins)
// fp32 accumulation; staging/dump identical to R4.
// ---------------------------------------------------------------------------
__device__ __forceinline__ void tap_acc(
    const uint4* __restrict__ base16, int pix, float w, float (&acc)[8])
{
    const uint4 u = __ldg(base16 + (size_t)pix * 32);
    const __half2* h = reinterpret_cast<const __half2*>(&u);
#pragma unroll
    for (int j = 0; j < 4; ++j) {
        const float2 f = __half22float2(h[j]);
        acc[j * 2 + 0] += w * f.x;
        acc[j * 2 + 1] += w * f.y;
    }
}

__device__ __forceinline__ void pool_phase_compute(
    const uint4* __restrict__ base16, float* __restrict__ s_out,
    const int (&i0)[2][14], const int (&i1)[2][14],
    const float (&wh)[2][14], const float (&wl)[2][14],
    int Wd, int q, int bs, int b0, int bcnt)
{
    for (int bb = bs; bb < bcnt; bb += 8) {
        const int bin = b0 + bb;
        const int py  = bin / 7;
        const int px  = bin - py * 7;
        float acc[8] = {0.f, 0.f, 0.f, 0.f, 0.f, 0.f, 0.f, 0.f};
#pragma unroll
        for (int sy = 0; sy < 2; ++sy) {
            const int   iy = py * 2 + sy;
            const int   r0 = i0[1][iy] * Wd;
            const int   r1 = i1[1][iy] * Wd;
            const float hy = wh[1][iy];
            const float ly = wl[1][iy];
#pragma unroll
            for (int sx = 0; sx < 2; ++sx) {
                const int   ix = px * 2 + sx;
                const int   x0 = i0[0][ix];
                const int   x1 = i1[0][ix];
                const float hx = wh[0][ix];
                const float lx = wl[0][ix];
                tap_acc(base16, r0 + x0, hy * hx, acc);
                tap_acc(base16, r0 + x1, hy * lx, acc);
                tap_acc(base16, r1 + x0, ly * hx, acc);
                tap_acc(base16, r1 + x1, ly * lx, acc);
            }
        }
        float4* s4 = reinterpret_cast<float4*>(s_out + bb * SPITCH + q * 8);
        s4[0] = make_float4(acc[0] * 0.25f, acc[1] * 0.25f, acc[2] * 0.25f, acc[3] * 0.25f);
        s4[1] = make_float4(acc[4] * 0.25f, acc[5] * 0.25f, acc[6] * 0.25f, acc[7] * 0.25f);
    }
}

template <int BCNT>
__device__ __forceinline__ void pool_phase_dump(
    const float* __restrict__ s_out, float* __restrict__ outm, int b0, int tid)
{
    const int cnt = BCNT * CCH;
    for (int i = tid; i < cnt; i += 256) {
        const int c  = i / BCNT;
        const int bb = i - c * BCNT;
        outm[c * NBINS + b0 + bb] = s_out[bb * SPITCH + c];
    }
}

__global__ __launch_bounds__(256) void roi_pool_kernel(
    const float* __restrict__ boxes, float* __restrict__ out, int R)
{
    __shared__ float s_out[25 * SPITCH];           // 26,000 B
    __shared__ int   s_i0[2][14], s_i1[2][14];
    __shared__ float s_h[2][14],  s_l[2][14];

    const int m   = blockIdx.x;
    const int tid = threadIdx.x;

    const float bx1 = __ldg(boxes + 4 * m + 0);
    const float by1 = __ldg(boxes + 4 * m + 1);
    const float bx2 = __ldg(boxes + 4 * m + 2);
    const float by2 = __ldg(boxes + 4 * m + 3);

    const float area = fmaxf((bx2 - bx1) * (by2 - by1), 0.0f);
    const float sz   = sqrtf(area);
    int lvl = (int)floorf(4.0f + log2f(sz / 224.0f + 1e-8f));
    lvl = min(max(lvl, 2), 5) - 2;                 // 0..3

    const int   Hd    = 256 >> lvl;
    const int   Wd    = Hd;
    const float scale = 0.25f / (float)(1 << lvl);
    const int   n     = m / R;

    const __half* fbase = g_nhwc + c_lvl_off[lvl] + (size_t)n * Hd * Wd * CCH;

    if (tid < 28) {
        const int axis = tid / 14;                 // 0 = x, 1 = y
        const int k    = tid - axis * 14;
        const float c1 = axis ? by1 : bx1;
        const float c2 = axis ? by2 : bx2;
        const int  lim = Hd;
        const float start = c1 * scale - 0.5f;
        const float bsz   = (c2 * scale - 0.5f - start) * (1.0f / 7.0f);
        const float off   = (float)(k >> 1) + ((k & 1) ? 0.75f : 0.25f);
        const float t     = start + off * bsz;
        const bool  v     = (t >= -1.0f) && (t <= (float)lim);
        const float tc    = fminf(fmaxf(t, 0.0f), (float)(lim - 1));
        const int   i0    = (int)tc;
        const int   i1    = min(i0 + 1, lim - 1);
        const float l     = tc - (float)i0;
        s_i0[axis][k] = i0;
        s_i1[axis][k] = i1;
        s_l[axis][k]  = v ? l : 0.0f;
        s_h[axis][k]  = v ? (1.0f - l) : 0.0f;
    }
    __syncthreads();

    const int q  = tid & 31;
    const int bs = tid >> 5;
    const uint4* base16 = reinterpret_cast<const uint4*>(fbase) + q;
    float* outm = out + (size_t)m * (NBINS * CCH);

    // phase 0: bins [0,25)
    pool_phase_compute(base16, s_out, s_i0, s_i1, s_h, s_l, Wd, q, bs, 0, 25);
    __syncthreads();
    pool_phase_dump<25>(s_out, outm, 0, tid);
    __syncthreads();

    // phase 1: bins [25,49)
    pool_phase_compute(base16, s_out, s_i0, s_i1, s_h, s_l, Wd, q, bs, 25, 24);
    __syncthreads();
    pool_phase_dump<24>(s_out, outm, 25, tid);
}

// ---------------------------------------------------------------------------
extern "C" void kernel_launch(void* const* d_in, const int* in_sizes, int n_in,
                              void* d_out, int out_size)
{
    const float* f0    = (const float*)d_in[0];
    const float* f1    = (const float*)d_in[1];
    const float* f2    = (const float*)d_in[2];
    const float* f3    = (const float*)d_in[3];
    const float* boxes = (const float*)d_in[4];
    float*       out   = (float*)d_out;

    const int M = in_sizes[4] / 4;   // 1024 boxes
    const int R = M / NIMG;          // 512 per image

    transpose_fused<<<dim3(T_CTAS, CCH / 32, NIMG), dim3(8, 32)>>>(f0, f1, f2, f3);
    roi_pool_kernel<<<M, 256>>>(boxes, out, R);
}

// round 7
// speedup vs baseline: 2.6137x; 1.2460x over previous
#include <cuda_runtime.h>
#include <cuda_fp16.h>

#define CCH 256        // channels (all levels)
#define NIMG 2         // batch
#define NBINS 49       // 7*7
#define SPITCH 260     // staging pitch in floats (CCH+4): 16B-aligned
#define NTAP 784       // 49 bins * 16 taps

// NHWC fp16 scratch for all 4 levels (element offsets):
// L0 @ 0, L1 @ 33,554,432, L2 @ 41,943,040, L3 @ 44,040,192 (44,564,480 halves = 89 MB)
__device__ __half g_nhwc[44564480];

__constant__ long long c_lvl_off[4] = {0LL, 33554432LL, 41943040LL, 44040192LL};

// ---------------------------------------------------------------------------
// Fused NCHW(fp32) -> NHWC(fp16) transpose, 4 hw-subtiles per CTA (MLP=4).
// blockIdx.x: L0 [0,512), L1 [512,640), L2 [640,672), L3 [672,680).
// blockIdx.y = channel tile (8), blockIdx.z = image (2). Block (8,32).
// ---------------------------------------------------------------------------
__global__ __launch_bounds__(256) void transpose_fused(
    const float* __restrict__ f0, const float* __restrict__ f1,
    const float* __restrict__ f2, const float* __restrict__ f3)
{
    __shared__ float tile[4][32][33];              // 16,896 B

    const int bx = blockIdx.x;
    int lvl, tb;
    const float* src;
    if (bx < 512)      { lvl = 0; tb = bx;       src = f0; }
    else if (bx < 640) { lvl = 1; tb = bx - 512; src = f1; }
    else if (bx < 672) { lvl = 2; tb = bx - 640; src = f2; }
    else               { lvl = 3; tb = bx - 672; src = f3; }

    const int HW  = (256 >> lvl) * (256 >> lvl);
    const int hw0 = tb * 128;
    const int c0  = blockIdx.y * 32;
    const int n   = blockIdx.z;
    const int tx  = threadIdx.x;   // 0..7
    const int ty  = threadIdx.y;   // 0..31

    const float* s = src + (size_t)n * CCH * HW + (size_t)(c0 + ty) * HW + hw0 + tx * 4;

#pragma unroll
    for (int j = 0; j < 4; ++j) {
        const float4 v = *reinterpret_cast<const float4*>(s + j * 32);
        tile[j][ty][tx * 4 + 0] = v.x;
        tile[j][ty][tx * 4 + 1] = v.y;
        tile[j][ty][tx * 4 + 2] = v.z;
        tile[j][ty][tx * 4 + 3] = v.w;
    }
    __syncthreads();

    __half* dst = g_nhwc + c_lvl_off[lvl] + (size_t)n * HW * CCH
                + (size_t)(hw0 + ty) * CCH + c0 + tx * 4;

#pragma unroll
    for (int j = 0; j < 4; ++j) {
        const __half2 a = __floats2half2_rn(tile[j][tx * 4 + 0][ty], tile[j][tx * 4 + 1][ty]);
        const __half2 b = __floats2half2_rn(tile[j][tx * 4 + 2][ty], tile[j][tx * 4 + 3][ty]);
        uint2 o;
        o.x = *reinterpret_cast<const unsigned int*>(&a);
        o.y = *reinterpret_cast<const unsigned int*>(&b);
        *reinterpret_cast<uint2*>(dst + (size_t)j * 32 * CCH) = o;
    }
}

// ---------------------------------------------------------------------------
// ROIAlign pooler over fp16 NHWC scratch. One CTA per box. 256 threads:
//   q  = tid & 31  -> channel oct (8 halves = one uint4), coalesced per warp
//   bs = tid >> 5  -> bin set; all lanes of a warp share one bin.
// Per-bin tap table (16 x {pixel offset, fp16 weight*0.25}) precomputed in
// smem once per CTA. Intra-sample bilinear combine in fp16 (HMUL2/HFMA2),
// per-sample convert to fp32, bin accumulation in fp32.
// ---------------------------------------------------------------------------
__global__ __launch_bounds__(256) void roi_pool_kernel(
    const float* __restrict__ boxes, float* __restrict__ out, int R)
{
    __shared__ float        s_out[25 * SPITCH];    // 26,000 B
    __shared__ int          s_toff[NTAP];          // 3,136 B
    __shared__ unsigned int s_twgt[NTAP];          // 3,136 B (broadcast half2)
    __shared__ int   s_i0[2][14], s_i1[2][14];
    __shared__ float s_h[2][14],  s_l[2][14];

    const int m   = blockIdx.x;
    const int tid = threadIdx.x;

    const float bx1 = __ldg(boxes + 4 * m + 0);
    const float by1 = __ldg(boxes + 4 * m + 1);
    const float bx2 = __ldg(boxes + 4 * m + 2);
    const float by2 = __ldg(boxes + 4 * m + 3);

    const float area = fmaxf((bx2 - bx1) * (by2 - by1), 0.0f);
    const float sz   = sqrtf(area);
    int lvl = (int)floorf(4.0f + log2f(sz / 224.0f + 1e-8f));
    lvl = min(max(lvl, 2), 5) - 2;                 // 0..3

    const int   Hd    = 256 >> lvl;
    const int   Wd    = Hd;
    const float scale = 0.25f / (float)(1 << lvl);
    const int   n     = m / R;

    const __half* fbase = g_nhwc + c_lvl_off[lvl] + (size_t)n * Hd * Wd * CCH;

    if (tid < 28) {
        const int axis = tid / 14;                 // 0 = x, 1 = y
        const int k    = tid - axis * 14;
        const float c1 = axis ? by1 : bx1;
        const float c2 = axis ? by2 : bx2;
        const int  lim = Hd;
        const float start = c1 * scale - 0.5f;
        const float bsz   = (c2 * scale - 0.5f - start) * (1.0f / 7.0f);
        const float off   = (float)(k >> 1) + ((k & 1) ? 0.75f : 0.25f);
        const float t     = start + off * bsz;
        const bool  v     = (t >= -1.0f) && (t <= (float)lim);
        const float tc    = fminf(fmaxf(t, 0.0f), (float)(lim - 1));
        const int   i0    = (int)tc;
        const int   i1    = min(i0 + 1, lim - 1);
        const float l     = tc - (float)i0;
        s_i0[axis][k] = i0;
        s_i1[axis][k] = i1;
        s_l[axis][k]  = v ? l : 0.0f;
        s_h[axis][k]  = v ? (1.0f - l) : 0.0f;
    }
    __syncthreads();

    // Build per-bin tap table: t = sample(2b: sy,sx)*4 + corner(2b: cy,cx).
    // Weight has the 0.25 sample-average folded in (exact, power of 2).
    for (int i = tid; i < NTAP; i += 256) {
        const int bin = i >> 4;
        const int t   = i & 15;
        const int py  = bin / 7;
        const int px  = bin - py * 7;
        const int iy  = py * 2 + (t >> 3);
        const int ix  = px * 2 + ((t >> 2) & 1);
        const int cy  = (t >> 1) & 1;
        const int cx  = t & 1;
        const int   yy = cy ? s_i1[1][iy] : s_i0[1][iy];
        const int   xx = cx ? s_i1[0][ix] : s_i0[0][ix];
        const float wy = cy ? s_l[1][iy]  : s_h[1][iy];
        const float wx = cx ? s_l[0][ix]  : s_h[0][ix];
        const __half2 w = __float2half2_rn(wy * wx * 0.25f);
        s_toff[i] = yy * Wd + xx;
        s_twgt[i] = *reinterpret_cast<const unsigned int*>(&w);
    }
    __syncthreads();

    const int q  = tid & 31;
    const int bs = tid >> 5;
    const uint4* base16 = reinterpret_cast<const uint4*>(fbase) + q;
    float* outm = out + (size_t)m * (NBINS * CCH);

#pragma unroll
    for (int phase = 0; phase < 2; ++phase) {
        const int b0   = phase * 25;
        const int bcnt = phase ? 24 : 25;

        for (int bb = bs; bb < bcnt; bb += 8) {
            const int tb = (b0 + bb) * 16;
            float2 facc[4] = {{0.f,0.f},{0.f,0.f},{0.f,0.f},{0.f,0.f}};
#pragma unroll
            for (int smp = 0; smp < 4; ++smp) {
                __half2 hacc[4];
#pragma unroll
                for (int t = 0; t < 4; ++t) {
                    const int          off = s_toff[tb + smp * 4 + t];
                    const unsigned int wb  = s_twgt[tb + smp * 4 + t];
                    const __half2 w = *reinterpret_cast<const __half2*>(&wb);
                    const uint4 u = __ldg(base16 + (size_t)off * 32);
                    const __half2* h = reinterpret_cast<const __half2*>(&u);
#pragma unroll
                    for (int j = 0; j < 4; ++j)
                        hacc[j] = (t == 0) ? __hmul2(h[j], w)
                                           : __hfma2(h[j], w, hacc[j]);
                }
#pragma unroll
                for (int j = 0; j < 4; ++j) {
                    const float2 f = __half22float2(hacc[j]);
                    facc[j].x += f.x;
                    facc[j].y += f.y;
                }
            }
            float4* s4 = reinterpret_cast<float4*>(s_out + bb * SPITCH + q * 8);
            s4[0] = make_float4(facc[0].x, facc[0].y, facc[1].x, facc[1].y);
            s4[1] = make_float4(facc[2].x, facc[2].y, facc[3].x, facc[3].y);
        }
        __syncthreads();

        // transposed dump: compile-time bin counts (magic-multiply div)
        if (phase == 0) {
            for (int i = tid; i < 25 * CCH; i += 256) {
                const int c  = i / 25;
                const int bb = i - c * 25;
                outm[c * NBINS + bb] = s_out[bb * SPITCH + c];
            }
        } else {
            for (int i = tid; i < 24 * CCH; i += 256) {
                const int c  = i / 24;
                const int bb = i - c * 24;
                outm[c * NBINS + 25 + bb] = s_out[bb * SPITCH + c];
            }
        }
        __syncthreads();
    }
}

// ---------------------------------------------------------------------------
extern "C" void kernel_launch(void* const* d_in, const int* in_sizes, int n_in,
                              void* d_out, int out_size)
{
    const float* f0    = (const float*)d_in[0];
    const float* f1    = (const float*)d_in[1];
    const float* f2    = (const float*)d_in[2];
    const float* f3    = (const float*)d_in[3];
    const float* boxes = (const float*)d_in[4];
    float*       out   = (float*)d_out;

    const int M = in_sizes[4] / 4;   // 1024 boxes
    const int R = M / NIMG;          // 512 per image

    transpose_fused<<<dim3(680, CCH / 32, NIMG), dim3(8, 32)>>>(f0, f1, f2, f3);
    roi_pool_kernel<<<M, 256>>>(boxes, out, R);
}

// round 8
// speedup vs baseline: 2.7232x; 1.0419x over previous
#include <cuda_runtime.h>
#include <cuda_fp16.h>

#define CCH 256        // channels (all levels)
#define NIMG 2         // batch
#define NBINS 49       // 7*7
#define SPITCH 260     // staging pitch in floats (CCH+4): 16B-aligned
#define HTAP 400       // 25 bins * 16 taps (per-phase table)

// NHWC fp16 scratch for all 4 levels (element offsets):
// L0 @ 0, L1 @ 33,554,432, L2 @ 41,943,040, L3 @ 44,040,192 (44,564,480 halves = 89 MB)
__device__ __half g_nhwc[44564480];

__constant__ long long c_lvl_off[4] = {0LL, 33554432LL, 41943040LL, 44040192LL};

// ---------------------------------------------------------------------------
// Fused NCHW(fp32) -> NHWC(fp16) transpose, 4 hw-subtiles per CTA (MLP=4).
// blockIdx.x: L0 [0,512), L1 [512,640), L2 [640,672), L3 [672,680).
// blockIdx.y = channel tile (8), blockIdx.z = image (2). Block (8,32).
// (Measured ~6.1 TB/s effective — at the streaming cap; unchanged from R7.)
// ---------------------------------------------------------------------------
__global__ __launch_bounds__(256) void transpose_fused(
    const float* __restrict__ f0, const float* __restrict__ f1,
    const float* __restrict__ f2, const float* __restrict__ f3)
{
    __shared__ float tile[4][32][33];              // 16,896 B

    const int bx = blockIdx.x;
    int lvl, tb;
    const float* src;
    if (bx < 512)      { lvl = 0; tb = bx;       src = f0; }
    else if (bx < 640) { lvl = 1; tb = bx - 512; src = f1; }
    else if (bx < 672) { lvl = 2; tb = bx - 640; src = f2; }
    else               { lvl = 3; tb = bx - 672; src = f3; }

    const int HW  = (256 >> lvl) * (256 >> lvl);
    const int hw0 = tb * 128;
    const int c0  = blockIdx.y * 32;
    const int n   = blockIdx.z;
    const int tx  = threadIdx.x;   // 0..7
    const int ty  = threadIdx.y;   // 0..31

    const float* s = src + (size_t)n * CCH * HW + (size_t)(c0 + ty) * HW + hw0 + tx * 4;

#pragma unroll
    for (int j = 0; j < 4; ++j) {
        const float4 v = *reinterpret_cast<const float4*>(s + j * 32);
        tile[j][ty][tx * 4 + 0] = v.x;
        tile[j][ty][tx * 4 + 1] = v.y;
        tile[j][ty][tx * 4 + 2] = v.z;
        tile[j][ty][tx * 4 + 3] = v.w;
    }
    __syncthreads();

    __half* dst = g_nhwc + c_lvl_off[lvl] + (size_t)n * HW * CCH
                + (size_t)(hw0 + ty) * CCH + c0 + tx * 4;

#pragma unroll
    for (int j = 0; j < 4; ++j) {
        const __half2 a = __floats2half2_rn(tile[j][tx * 4 + 0][ty], tile[j][tx * 4 + 1][ty]);
        const __half2 b = __floats2half2_rn(tile[j][tx * 4 + 2][ty], tile[j][tx * 4 + 3][ty]);
        uint2 o;
        o.x = *reinterpret_cast<const unsigned int*>(&a);
        o.y = *reinterpret_cast<const unsigned int*>(&b);
        *reinterpret_cast<uint2*>(dst + (size_t)j * 32 * CCH) = o;
    }
}

// ---------------------------------------------------------------------------
// ROIAlign pooler over fp16 NHWC scratch. TWO CTAs per box:
//   bid = m*2 + phase; phase 0 -> bins [0,25), phase 1 -> bins [25,49).
// 256 threads: q = tid & 31 -> channel oct (uint4 of 8 halves), coalesced;
// bs = tid >> 5 -> bin set (all lanes of a warp share one bin).
// Per-bin tap table packed as uint2 {pixel offset, fp16 weight*0.25 (x2)}
// -> one LDS.64 broadcast per tap. fp16 intra-sample bilinear (HMUL2/HFMA2),
// per-sample fp32 convert, fp32 bin accumulation. Staged [bin][channel] in
// smem, dumped transposed to out[m][c][bin].
// ---------------------------------------------------------------------------
__global__ __launch_bounds__(256) void roi_pool_kernel(
    const float* __restrict__ boxes, float* __restrict__ out, int R)
{
    __shared__ float s_out[25 * SPITCH];           // 26,000 B
    __shared__ uint2 s_tap[HTAP];                  // 3,200 B
    __shared__ int   s_i0[2][14], s_i1[2][14];
    __shared__ float s_h[2][14],  s_l[2][14];

    const int bid   = blockIdx.x;
    const int m     = bid >> 1;
    const int phase = bid & 1;
    const int tid   = threadIdx.x;

    const int b0   = phase ? 25 : 0;
    const int bcnt = phase ? 24 : 25;

    const float bx1 = __ldg(boxes + 4 * m + 0);
    const float by1 = __ldg(boxes + 4 * m + 1);
    const float bx2 = __ldg(boxes + 4 * m + 2);
    const float by2 = __ldg(boxes + 4 * m + 3);

    const float area = fmaxf((bx2 - bx1) * (by2 - by1), 0.0f);
    const float sz   = sqrtf(area);
    int lvl = (int)floorf(4.0f + log2f(sz / 224.0f + 1e-8f));
    lvl = min(max(lvl, 2), 5) - 2;                 // 0..3

    const int   Hd    = 256 >> lvl;
    const int   Wd    = Hd;
    const float scale = 0.25f / (float)(1 << lvl);
    const int   n     = m / R;

    const __half* fbase = g_nhwc + c_lvl_off[lvl] + (size_t)n * Hd * Wd * CCH;

    if (tid < 28) {
        const int axis = tid / 14;                 // 0 = x, 1 = y
        const int k    = tid - axis * 14;
        const float c1 = axis ? by1 : bx1;
        const float c2 = axis ? by2 : bx2;
        const int  lim = Hd;
        const float start = c1 * scale - 0.5f;
        const float bsz   = (c2 * scale - 0.5f - start) * (1.0f / 7.0f);
        const float off   = (float)(k >> 1) + ((k & 1) ? 0.75f : 0.25f);
        const float t     = start + off * bsz;
        const bool  v     = (t >= -1.0f) && (t <= (float)lim);
        const float tc    = fminf(fmaxf(t, 0.0f), (float)(lim - 1));
        const int   i0    = (int)tc;
        const int   i1    = min(i0 + 1, lim - 1);
        const float l     = tc - (float)i0;
        s_i0[axis][k] = i0;
        s_i1[axis][k] = i1;
        s_l[axis][k]  = v ? l : 0.0f;
        s_h[axis][k]  = v ? (1.0f - l) : 0.0f;
    }
    __syncthreads();

    // Tap table for THIS phase's bins: entry index i -> local bin i>>4, tap i&15.
    // tap bits: [3]=sy, [2]=sx, [1]=cy, [0]=cx. 0.25 sample-average folded in.
    for (int i = tid; i < bcnt * 16; i += 256) {
        const int bin = b0 + (i >> 4);
        const int t   = i & 15;
        const int py  = bin / 7;
        const int px  = bin - py * 7;
        const int iy  = py * 2 + (t >> 3);
        const int ix  = px * 2 + ((t >> 2) & 1);
        const int cy  = (t >> 1) & 1;
        const int cx  = t & 1;
        const int   yy = cy ? s_i1[1][iy] : s_i0[1][iy];
        const int   xx = cx ? s_i1[0][ix] : s_i0[0][ix];
        const float wy = cy ? s_l[1][iy]  : s_h[1][iy];
        const float wx = cx ? s_l[0][ix]  : s_h[0][ix];
        const __half2 w = __float2half2_rn(wy * wx * 0.25f);
        uint2 e;
        e.x = (unsigned int)(yy * Wd + xx);
        e.y = *reinterpret_cast<const unsigned int*>(&w);
        s_tap[i] = e;
    }
    __syncthreads();

    const int q  = tid & 31;
    const int bs = tid >> 5;
    const uint4* base16 = reinterpret_cast<const uint4*>(fbase) + q;
    float* outm = out + (size_t)m * (NBINS * CCH);

    for (int bb = bs; bb < bcnt; bb += 8) {
        const int tb = bb * 16;
        float2 facc[4] = {{0.f,0.f},{0.f,0.f},{0.f,0.f},{0.f,0.f}};
#pragma unroll
        for (int smp = 0; smp < 4; ++smp) {
            __half2 hacc[4];
#pragma unroll
            for (int t = 0; t < 4; ++t) {
                const uint2 e = s_tap[tb + smp * 4 + t];   // LDS.64 broadcast
                const __half2 w = *reinterpret_cast<const __half2*>(&e.y);
                const uint4 u = __ldg(base16 + (size_t)e.x * 32);
                const __half2* h = reinterpret_cast<const __half2*>(&u);
#pragma unroll
                for (int j = 0; j < 4; ++j)
                    hacc[j] = (t == 0) ? __hmul2(h[j], w)
                                       : __hfma2(h[j], w, hacc[j]);
            }
#pragma unroll
            for (int j = 0; j < 4; ++j) {
                const float2 f = __half22float2(hacc[j]);
                facc[j].x += f.x;
                facc[j].y += f.y;
            }
        }
        float4* s4 = reinterpret_cast<float4*>(s_out + bb * SPITCH + q * 8);
        s4[0] = make_float4(facc[0].x, facc[0].y, facc[1].x, facc[1].y);
        s4[1] = make_float4(facc[2].x, facc[2].y, facc[3].x, facc[3].y);
    }
    __syncthreads();

    // Transposed dump: compile-time bin counts (magic-multiply div).
    if (phase == 0) {
        for (int i = tid; i < 25 * CCH; i += 256) {
            const int c  = i / 25;
            const int bb = i - c * 25;
            outm[c * NBINS + bb] = s_out[bb * SPITCH + c];
        }
    } else {
        for (int i = tid; i < 24 * CCH; i += 256) {
            const int c  = i / 24;
            const int bb = i - c * 24;
            outm[c * NBINS + 25 + bb] = s_out[bb * SPITCH + c];
        }
    }
}

// ---------------------------------------------------------------------------
extern "C" void kernel_launch(void* const* d_in, const int* in_sizes, int n_in,
                              void* d_out, int out_size)
{
    const float* f0    = (const float*)d_in[0];
    const float* f1    = (const float*)d_in[1];
    const float* f2    = (const float*)d_in[2];
    const float* f3    = (const float*)d_in[3];
    const float* boxes = (const float*)d_in[4];
    float*       out   = (float*)d_out;

    const int M = in_sizes[4] / 4;   // 1024 boxes
    const int R = M / NIMG;          // 512 per image

    transpose_fused<<<dim3(680, CCH / 32, NIMG), dim3(8, 32)>>>(f0, f1, f2, f3);
    roi_pool_kernel<<<M * 2, 256>>>(boxes, out, R);
}